// round 5
// baseline (speedup 1.0000x reference)
#include <cuda_runtime.h>
#include <cstdint>
#include <cstddef>

// Problem constants
#define PB   4
#define PN   2048
#define PDIM 1024
#define PH   16
#define PHD  64
#define PSCALE 0.125f           // HEAD_DIM^-0.5

// Scratch (allocation-free rule: __device__ globals)
__device__ float g_qkv[(size_t)PB * PN * 3 * PDIM];   // [B, N, 3*DIM]  ~100 MB (fp32)
__device__ float g_attn[(size_t)PB * PN * PDIM];      // [B, N, DIM]    ~33 MB (tf32-valued)
__device__ float g_xr[(size_t)PB * PN * PDIM];        // x rounded to tf32  ~33 MB
__device__ float g_wt[(size_t)4 * PDIM * PDIM];       // transposed+rounded weights ~16 MB

// ===========================================================================
// Helpers (baseline PTX only — no 'a'-gated features)
// ===========================================================================
__device__ __forceinline__ uint32_t smem_u32(const void* p) {
    uint32_t a;
    asm("{ .reg .u64 t; cvta.to.shared.u64 t, %1; cvt.u32.u64 %0, t; }" : "=r"(a) : "l"(p));
    return a;
}
__device__ __forceinline__ uint32_t f2tf32(float v) {
    uint32_t r;
    asm("cvt.rna.tf32.f32 %0, %1;" : "=r"(r) : "f"(v));
    return r;
}
__device__ __forceinline__ void cp_async16(uint32_t saddr, const void* gptr) {
    asm volatile("cp.async.cg.shared.global [%0], [%1], 16;" :: "r"(saddr), "l"(gptr));
}
#define CP_COMMIT() asm volatile("cp.async.commit_group;" ::: "memory")
#define CP_WAIT1()  asm volatile("cp.async.wait_group 1;" ::: "memory")

// D += A*B  (m16n8k8, tf32, row.col)
__device__ __forceinline__ void mma_tf32(float* d, const uint32_t* a, const uint32_t* b) {
    asm volatile(
        "mma.sync.aligned.m16n8k8.row.col.f32.tf32.tf32.f32 "
        "{%0,%1,%2,%3}, {%4,%5,%6,%7}, {%8,%9}, {%0,%1,%2,%3};"
        : "+f"(d[0]), "+f"(d[1]), "+f"(d[2]), "+f"(d[3])
        : "r"(a[0]), "r"(a[1]), "r"(a[2]), "r"(a[3]), "r"(b[0]), "r"(b[1]));
}

// ===========================================================================
// Pre-round fp32 -> tf32-valued fp32 (vectorized)
// ===========================================================================
__global__ void round_tf32_kernel(const float* __restrict__ in, float* __restrict__ out, int n4)
{
    int i = blockIdx.x * blockDim.x + threadIdx.x;
    if (i < n4) {
        float4 v = ((const float4*)in)[i];
        uint4 r;
        r.x = f2tf32(v.x); r.y = f2tf32(v.y); r.z = f2tf32(v.z); r.w = f2tf32(v.w);
        ((uint4*)out)[i] = r;
    }
}

// ===========================================================================
// Transpose + round: out[C][R] = tf32(in[R][C])
// ===========================================================================
__global__ void transpose_kernel(const float* __restrict__ in, float* __restrict__ out,
                                 int R, int C)
{
    __shared__ float t[32][33];
    int bx = blockIdx.x, by = blockIdx.y;
    int tx = threadIdx.x, ty = threadIdx.y;
#pragma unroll
    for (int j = 0; j < 32; j += 8)
        t[ty + j][tx] = in[(size_t)(by * 32 + ty + j) * C + bx * 32 + tx];
    __syncthreads();
#pragma unroll
    for (int j = 0; j < 32; j += 8)
        out[(size_t)(bx * 32 + ty + j) * R + by * 32 + tx] =
            __uint_as_float(f2tf32(t[tx][ty + j]));
}

// ===========================================================================
// tf32 mma.sync GEMM:  C[M, Ncols] = A[M, K] @ Bt[Ncols, K]^T  (+ bias)
// A, Bt row-major, values already tf32-rounded.
// Tile 128x128, BK=16, 3-stage cp.async pipeline, 256 threads (8 warps, 2x4),
// warp tile 64x32, m16n8k8 fragments. SMEM row stride 20 floats (skew),
// conflict-free for the fragment LDS pattern.
// ===========================================================================
#define GEMM_BK      16
#define GEMM_STRIDE  20                          // floats per smem row
#define GEMM_TILE_B  (128 * GEMM_STRIDE * 4)     // 10240 bytes (one operand)
#define GEMM_STAGE_B (2 * GEMM_TILE_B)           // 20480
#define GEMM_NSTAGE  3
#define GEMM_SMEM    (GEMM_NSTAGE * GEMM_STAGE_B)  // 61440

__global__ __launch_bounds__(256)
void gemm_mma_kernel(const float* __restrict__ A, const float* __restrict__ Bt,
                     float* __restrict__ C, int M, int Ncols, int K,
                     const float* __restrict__ bias)
{
    extern __shared__ char smem[];
    const uint32_t smem_base = smem_u32(smem);
    const int tid = threadIdx.x;
    const int wid = tid >> 5;
    const int lid = tid & 31;
    const int warp_m = wid & 1;        // 2 warp-rows (64 rows each)
    const int warp_n = wid >> 1;       // 4 warp-cols (32 cols each)
    const int g   = lid >> 2;          // group id 0..7
    const int tig = lid & 3;           // thread in group 0..3
    const int bx = blockIdx.x, by = blockIdx.y;

    const float* Ab = A  + (size_t)(by * 128) * K;
    const float* Bb = Bt + (size_t)(bx * 128) * K;

    // per-thread cp.async mapping: 512 16B chunks per operand, 2 per thread
    const int ch0 = tid, ch1 = tid + 256;
    const int r0 = ch0 >> 2, c0 = (ch0 & 3);   // row, 16B-chunk-in-row
    const int r1 = ch1 >> 2, c1 = (ch1 & 3);

    float acc[4][4][4];
#pragma unroll
    for (int mi = 0; mi < 4; mi++)
#pragma unroll
        for (int ni = 0; ni < 4; ni++)
#pragma unroll
            for (int j = 0; j < 4; j++) acc[mi][ni][j] = 0.0f;

    const int niter = K / GEMM_BK;     // 64 or 64

    // issue loads for stage s covering k-chunk `it`
    auto issue = [&](int s, int it) {
        const uint32_t sa = smem_base + s * GEMM_STAGE_B;
        const uint32_t sb = sa + GEMM_TILE_B;
        const size_t k0 = (size_t)it * GEMM_BK;
        cp_async16(sa + r0 * 80 + c0 * 16, Ab + (size_t)r0 * K + k0 + c0 * 4);
        cp_async16(sa + r1 * 80 + c1 * 16, Ab + (size_t)r1 * K + k0 + c1 * 4);
        cp_async16(sb + r0 * 80 + c0 * 16, Bb + (size_t)r0 * K + k0 + c0 * 4);
        cp_async16(sb + r1 * 80 + c1 * 16, Bb + (size_t)r1 * K + k0 + c1 * 4);
    };

    // prologue: stages 0, 1
    issue(0, 0); CP_COMMIT();
    issue(1, 1); CP_COMMIT();

    for (int it = 0; it < niter; it++) {
        CP_WAIT1();            // group for stage `it` complete
        __syncthreads();       // visible to all threads; buffer (it+2)%3 reusable
        if (it + 2 < niter) issue((it + 2) % GEMM_NSTAGE, it + 2);
        CP_COMMIT();           // commit every iter (possibly empty) to keep counting

        const int s = it % GEMM_NSTAGE;
        const float* As = (const float*)(smem + s * GEMM_STAGE_B);
        const float* Bs = As + 128 * GEMM_STRIDE;

#pragma unroll
        for (int kk = 0; kk < GEMM_BK; kk += 8) {
            uint32_t afr[4][4];
#pragma unroll
            for (int mi = 0; mi < 4; mi++) {
                const int row = warp_m * 64 + mi * 16 + g;
                const float* ap0 = As + row * GEMM_STRIDE + kk + tig;
                const float* ap1 = ap0 + 8 * GEMM_STRIDE;
                afr[mi][0] = __float_as_uint(ap0[0]);
                afr[mi][1] = __float_as_uint(ap1[0]);
                afr[mi][2] = __float_as_uint(ap0[4]);
                afr[mi][3] = __float_as_uint(ap1[4]);
            }
            uint32_t bfr[4][2];
#pragma unroll
            for (int ni = 0; ni < 4; ni++) {
                const int col = warp_n * 32 + ni * 8 + g;
                const float* bp = Bs + col * GEMM_STRIDE + kk + tig;
                bfr[ni][0] = __float_as_uint(bp[0]);
                bfr[ni][1] = __float_as_uint(bp[4]);
            }
#pragma unroll
            for (int mi = 0; mi < 4; mi++)
#pragma unroll
                for (int ni = 0; ni < 4; ni++)
                    mma_tf32(acc[mi][ni], afr[mi], bfr[ni]);
        }
    }

    // epilogue: c0,c1 at (row, 2*tig), c2,c3 at (row+8, 2*tig)
#pragma unroll
    for (int mi = 0; mi < 4; mi++) {
#pragma unroll
        for (int ni = 0; ni < 4; ni++) {
            const int row = by * 128 + warp_m * 64 + mi * 16 + g;
            const int col = bx * 128 + warp_n * 32 + ni * 8 + tig * 2;
            float2 v0 = make_float2(acc[mi][ni][0], acc[mi][ni][1]);
            float2 v1 = make_float2(acc[mi][ni][2], acc[mi][ni][3]);
            if (bias) {
                float2 bb = *(const float2*)(bias + col);
                v0.x += bb.x; v0.y += bb.y;
                v1.x += bb.x; v1.y += bb.y;
            }
            *(float2*)(C + (size_t)row * Ncols + col) = v0;
            *(float2*)(C + (size_t)(row + 8) * Ncols + col) = v1;
        }
    }
}

// ---------------------------------------------------------------------------
// Flash-attention style kernel (fp32, online softmax) — as R1, but the
// output is rounded to tf32 (it feeds the proj GEMM as operand A).
// ---------------------------------------------------------------------------
__global__ __launch_bounds__(256, 2)
void attn_kernel(const float* __restrict__ qkv, float* __restrict__ outp)
{
    __shared__ __align__(16) float Qs[64][64];
    __shared__ float            Ks[32][65];
    __shared__ __align__(16) float Vs[32][64];
    __shared__ float            Ps[64][33];
    __shared__ float row_m[64], row_l[64], row_corr[64];

    const int tid = threadIdx.x;
    const int qt  = blockIdx.x;
    const int h   = blockIdx.y;
    const int b   = blockIdx.z;

    const size_t rstride = 3 * PDIM;
    const float* qb = qkv + ((size_t)(b * PN) + qt * 64) * rstride + h * PHD;

#pragma unroll
    for (int i = 0; i < 4; i++) {
        int e = tid + i * 256;
        int r = e >> 4;
        int d = (e & 15) * 4;
        float4 v = *(const float4*)(qb + (size_t)r * rstride + d);
        v.x *= PSCALE; v.y *= PSCALE; v.z *= PSCALE; v.w *= PSCALE;
        *(float4*)&Qs[r][d] = v;
    }
    if (tid < 64) { row_m[tid] = -1e30f; row_l[tid] = 0.0f; }

    float o[4][4];
#pragma unroll
    for (int i = 0; i < 4; i++)
#pragma unroll
        for (int j = 0; j < 4; j++) o[i][j] = 0.0f;

    const int tx = tid & 15;
    const int ty = tid >> 4;
    const int sx = tid & 7;
    const int sy = tid >> 3;
    __syncthreads();

    for (int j0 = 0; j0 < PN; j0 += 32) {
        const float* kb = qkv + ((size_t)(b * PN) + j0) * rstride + PDIM + h * PHD;
        const float* vb = kb + PDIM;
#pragma unroll
        for (int i = 0; i < 2; i++) {
            int e = tid + i * 256;
            int r = e >> 4;
            int d = (e & 15) * 4;
            float4 k4 = *(const float4*)(kb + (size_t)r * rstride + d);
            Ks[r][d + 0] = k4.x; Ks[r][d + 1] = k4.y;
            Ks[r][d + 2] = k4.z; Ks[r][d + 3] = k4.w;
            float4 v4 = *(const float4*)(vb + (size_t)r * rstride + d);
            *(float4*)&Vs[r][d] = v4;
        }
        __syncthreads();

        {
            const int r0 = sy * 2, c0 = sx * 4;
            float s[2][4];
#pragma unroll
            for (int i = 0; i < 2; i++)
#pragma unroll
                for (int jj = 0; jj < 4; jj++) s[i][jj] = 0.0f;
#pragma unroll 8
            for (int k = 0; k < 64; k++) {
                float q0 = Qs[r0][k];
                float q1 = Qs[r0 + 1][k];
#pragma unroll
                for (int jj = 0; jj < 4; jj++) {
                    float kv = Ks[c0 + jj][k];
                    s[0][jj] = fmaf(q0, kv, s[0][jj]);
                    s[1][jj] = fmaf(q1, kv, s[1][jj]);
                }
            }
#pragma unroll
            for (int i = 0; i < 2; i++)
#pragma unroll
                for (int jj = 0; jj < 4; jj++)
                    Ps[r0 + i][c0 + jj] = s[i][jj];
        }
        __syncthreads();

        if (tid < 64) {
            const int r = tid;
            float mx = row_m[r];
            float tm = -1e30f;
#pragma unroll
            for (int c = 0; c < 32; c++) tm = fmaxf(tm, Ps[r][c]);
            float nm   = fmaxf(mx, tm);
            float corr = __expf(mx - nm);
            float sum  = 0.0f;
#pragma unroll
            for (int c = 0; c < 32; c++) {
                float p = __expf(Ps[r][c] - nm);
                Ps[r][c] = p;
                sum += p;
            }
            row_l[r]    = row_l[r] * corr + sum;
            row_m[r]    = nm;
            row_corr[r] = corr;
        }
        __syncthreads();

        {
            const int r0 = ty * 4, d0 = tx * 4;
            float c0f = row_corr[r0 + 0], c1f = row_corr[r0 + 1];
            float c2f = row_corr[r0 + 2], c3f = row_corr[r0 + 3];
#pragma unroll
            for (int jj = 0; jj < 4; jj++) {
                o[0][jj] *= c0f; o[1][jj] *= c1f;
                o[2][jj] *= c2f; o[3][jj] *= c3f;
            }
#pragma unroll 8
            for (int c = 0; c < 32; c++) {
                float4 vv = *(const float4*)&Vs[c][d0];
                float p0 = Ps[r0 + 0][c], p1 = Ps[r0 + 1][c];
                float p2 = Ps[r0 + 2][c], p3 = Ps[r0 + 3][c];
                o[0][0] = fmaf(p0, vv.x, o[0][0]); o[0][1] = fmaf(p0, vv.y, o[0][1]);
                o[0][2] = fmaf(p0, vv.z, o[0][2]); o[0][3] = fmaf(p0, vv.w, o[0][3]);
                o[1][0] = fmaf(p1, vv.x, o[1][0]); o[1][1] = fmaf(p1, vv.y, o[1][1]);
                o[1][2] = fmaf(p1, vv.z, o[1][2]); o[1][3] = fmaf(p1, vv.w, o[1][3]);
                o[2][0] = fmaf(p2, vv.x, o[2][0]); o[2][1] = fmaf(p2, vv.y, o[2][1]);
                o[2][2] = fmaf(p2, vv.z, o[2][2]); o[2][3] = fmaf(p2, vv.w, o[2][3]);
                o[3][0] = fmaf(p3, vv.x, o[3][0]); o[3][1] = fmaf(p3, vv.y, o[3][1]);
                o[3][2] = fmaf(p3, vv.z, o[3][2]); o[3][3] = fmaf(p3, vv.w, o[3][3]);
            }
        }
        __syncthreads();
    }

    {
        const int r0 = ty * 4, d0 = tx * 4;
        float* ob = outp + ((size_t)(b * PN) + qt * 64) * PDIM + h * PHD;
#pragma unroll
        for (int i = 0; i < 4; i++) {
            float inv = 1.0f / row_l[r0 + i];
            float4 v;
            v.x = __uint_as_float(f2tf32(o[i][0] * inv));
            v.y = __uint_as_float(f2tf32(o[i][1] * inv));
            v.z = __uint_as_float(f2tf32(o[i][2] * inv));
            v.w = __uint_as_float(f2tf32(o[i][3] * inv));
            *(float4*)(ob + (size_t)(r0 + i) * PDIM + d0) = v;
        }
    }
}

// ---------------------------------------------------------------------------
// Launch
// ---------------------------------------------------------------------------
extern "C" void kernel_launch(void* const* d_in, const int* in_sizes, int n_in,
                              void* d_out, int out_size)
{
    const float* x      = (const float*)d_in[0];   // [4, 2048, 1024]
    const float* w_qkv  = (const float*)d_in[1];   // [1024, 3072]
    const float* w_proj = (const float*)d_in[2];   // [1024, 1024]
    const float* b_proj = (const float*)d_in[3];   // [1024]
    float* out = (float*)d_out;                    // [4, 2048, 1024]

    float *qkv = nullptr, *att = nullptr, *xr = nullptr, *wt = nullptr;
    cudaGetSymbolAddress((void**)&qkv, g_qkv);
    cudaGetSymbolAddress((void**)&att, g_attn);
    cudaGetSymbolAddress((void**)&xr,  g_xr);
    cudaGetSymbolAddress((void**)&wt,  g_wt);
    float* wqkvT  = wt;                             // [3072, 1024]
    float* wprojT = wt + (size_t)3 * PDIM * PDIM;   // [1024, 1024]

    cudaFuncSetAttribute(gemm_mma_kernel,
                         cudaFuncAttributeMaxDynamicSharedMemorySize, GEMM_SMEM);

    const int M = PB * PN;          // 8192

    // 0) pre-round x; transpose+round weights (K-major operands, tf32-valued)
    {
        int n4 = (int)((size_t)M * PDIM / 4);
        round_tf32_kernel<<<(n4 + 255) / 256, 256>>>(x, xr, n4);
        dim3 blk(32, 8);
        transpose_kernel<<<dim3(3 * PDIM / 32, PDIM / 32), blk>>>(w_qkv, wqkvT, PDIM, 3 * PDIM);
        transpose_kernel<<<dim3(PDIM / 32, PDIM / 32), blk>>>(w_proj, wprojT, PDIM, PDIM);
    }

    // 1) qkv = x @ w_qkv  (tf32 mma.sync)
    {
        dim3 grid(3 * PDIM / 128, M / 128);
        gemm_mma_kernel<<<grid, 256, GEMM_SMEM>>>(xr, wqkvT, qkv, M, 3 * PDIM, PDIM, nullptr);
    }

    // 2) attention per (b, h, qtile)
    {
        dim3 grid(PN / 64, PH, PB);
        attn_kernel<<<grid, 256>>>(qkv, att);
    }

    // 3) out = att @ w_proj + b_proj  (tf32 mma.sync)
    {
        dim3 grid(PDIM / 128, M / 128);
        gemm_mma_kernel<<<grid, 256, GEMM_SMEM>>>(att, wprojT, out, M, PDIM, PDIM, b_proj);
    }
}

// round 6
// speedup vs baseline: 4.2269x; 4.2269x over previous
#include <cuda_runtime.h>
#include <cstdint>
#include <cstddef>

// Problem constants
#define PB   4
#define PN   2048
#define PDIM 1024
#define PH   16
#define PHD  64
#define PSCALE 0.125f           // HEAD_DIM^-0.5

// Scratch (allocation-free rule: __device__ globals)
__device__ float g_qkv[(size_t)PB * PN * 3 * PDIM];   // [B, N, 3*DIM]
__device__ float g_attn[(size_t)PB * PN * PDIM];      // [B, N, DIM] (tf32-valued)
__device__ float g_xr[(size_t)PB * PN * PDIM];        // x rounded to tf32
__device__ float g_wt[(size_t)4 * PDIM * PDIM];       // transposed+rounded weights

// ===========================================================================
// Helpers (baseline PTX only — no 'a'-gated features)
// ===========================================================================
__device__ __forceinline__ uint32_t smem_u32(const void* p) {
    uint32_t a;
    asm("{ .reg .u64 t; cvta.to.shared.u64 t, %1; cvt.u32.u64 %0, t; }" : "=r"(a) : "l"(p));
    return a;
}
__device__ __forceinline__ uint32_t f2tf32(float v) {
    uint32_t r;
    asm("cvt.rna.tf32.f32 %0, %1;" : "=r"(r) : "f"(v));
    return r;
}
__device__ __forceinline__ void cp_async16(uint32_t saddr, const void* gptr) {
    asm volatile("cp.async.cg.shared.global [%0], [%1], 16;" :: "r"(saddr), "l"(gptr));
}
#define CP_COMMIT() asm volatile("cp.async.commit_group;" ::: "memory")
#define CP_WAIT1()  asm volatile("cp.async.wait_group 1;" ::: "memory")

// D += A*B  (m16n8k8, tf32, row.col)
__device__ __forceinline__ void mma_tf32(float* d, const uint32_t* a, const uint32_t* b) {
    asm volatile(
        "mma.sync.aligned.m16n8k8.row.col.f32.tf32.tf32.f32 "
        "{%0,%1,%2,%3}, {%4,%5,%6,%7}, {%8,%9}, {%0,%1,%2,%3};"
        : "+f"(d[0]), "+f"(d[1]), "+f"(d[2]), "+f"(d[3])
        : "r"(a[0]), "r"(a[1]), "r"(a[2]), "r"(a[3]), "r"(b[0]), "r"(b[1]));
}

// Fast 2^t on the FMA pipe (no MUFU). t <= 0 expected; clamped at -126.
__device__ __forceinline__ float exp2_fast(float t) {
    t = fmaxf(t, -126.0f);
    int n = __float2int_rn(t);
    float f = t - (float)n;                      // f in [-0.5, 0.5]
    float p = 1.0f + f * (0.6931472f + f * (0.2402265f + f * (0.0555041f + f * 0.0096784f)));
    return __uint_as_float(__float_as_uint(p) + ((uint32_t)n << 23));
}

// ===========================================================================
// Pre-round fp32 -> tf32-valued fp32 (vectorized)
// ===========================================================================
__global__ void round_tf32_kernel(const float* __restrict__ in, float* __restrict__ out, int n4)
{
    int i = blockIdx.x * blockDim.x + threadIdx.x;
    if (i < n4) {
        float4 v = ((const float4*)in)[i];
        uint4 r;
        r.x = f2tf32(v.x); r.y = f2tf32(v.y); r.z = f2tf32(v.z); r.w = f2tf32(v.w);
        ((uint4*)out)[i] = r;
    }
}

// ===========================================================================
// Transpose + round: out[C][R] = tf32(in[R][C])
// ===========================================================================
__global__ void transpose_kernel(const float* __restrict__ in, float* __restrict__ out,
                                 int R, int C)
{
    __shared__ float t[32][33];
    int bx = blockIdx.x, by = blockIdx.y;
    int tx = threadIdx.x, ty = threadIdx.y;
#pragma unroll
    for (int j = 0; j < 32; j += 8)
        t[ty + j][tx] = in[(size_t)(by * 32 + ty + j) * C + bx * 32 + tx];
    __syncthreads();
#pragma unroll
    for (int j = 0; j < 32; j += 8)
        out[(size_t)(bx * 32 + ty + j) * R + by * 32 + tx] =
            __uint_as_float(f2tf32(t[tx][ty + j]));
}

// ===========================================================================
// tf32 mma.sync GEMM (unchanged from R5 — validated):
// C[M, Ncols] = A[M, K] @ Bt[Ncols, K]^T  (+ bias)
// ===========================================================================
#define GEMM_BK      16
#define GEMM_STRIDE  20
#define GEMM_TILE_B  (128 * GEMM_STRIDE * 4)
#define GEMM_STAGE_B (2 * GEMM_TILE_B)
#define GEMM_NSTAGE  3
#define GEMM_SMEM    (GEMM_NSTAGE * GEMM_STAGE_B)

__global__ __launch_bounds__(256)
void gemm_mma_kernel(const float* __restrict__ A, const float* __restrict__ Bt,
                     float* __restrict__ C, int M, int Ncols, int K,
                     const float* __restrict__ bias)
{
    extern __shared__ char smem[];
    const uint32_t smem_base = smem_u32(smem);
    const int tid = threadIdx.x;
    const int wid = tid >> 5;
    const int lid = tid & 31;
    const int warp_m = wid & 1;
    const int warp_n = wid >> 1;
    const int g   = lid >> 2;
    const int tig = lid & 3;
    const int bx = blockIdx.x, by = blockIdx.y;

    const float* Ab = A  + (size_t)(by * 128) * K;
    const float* Bb = Bt + (size_t)(bx * 128) * K;

    const int ch0 = tid, ch1 = tid + 256;
    const int r0 = ch0 >> 2, c0 = (ch0 & 3);
    const int r1 = ch1 >> 2, c1 = (ch1 & 3);

    float acc[4][4][4];
#pragma unroll
    for (int mi = 0; mi < 4; mi++)
#pragma unroll
        for (int ni = 0; ni < 4; ni++)
#pragma unroll
            for (int j = 0; j < 4; j++) acc[mi][ni][j] = 0.0f;

    const int niter = K / GEMM_BK;

    auto issue = [&](int s, int it) {
        const uint32_t sa = smem_base + s * GEMM_STAGE_B;
        const uint32_t sb = sa + GEMM_TILE_B;
        const size_t k0 = (size_t)it * GEMM_BK;
        cp_async16(sa + r0 * 80 + c0 * 16, Ab + (size_t)r0 * K + k0 + c0 * 4);
        cp_async16(sa + r1 * 80 + c1 * 16, Ab + (size_t)r1 * K + k0 + c1 * 4);
        cp_async16(sb + r0 * 80 + c0 * 16, Bb + (size_t)r0 * K + k0 + c0 * 4);
        cp_async16(sb + r1 * 80 + c1 * 16, Bb + (size_t)r1 * K + k0 + c1 * 4);
    };

    issue(0, 0); CP_COMMIT();
    issue(1, 1); CP_COMMIT();

    for (int it = 0; it < niter; it++) {
        CP_WAIT1();
        __syncthreads();
        if (it + 2 < niter) issue((it + 2) % GEMM_NSTAGE, it + 2);
        CP_COMMIT();

        const int s = it % GEMM_NSTAGE;
        const float* As = (const float*)(smem + s * GEMM_STAGE_B);
        const float* Bs = As + 128 * GEMM_STRIDE;

#pragma unroll
        for (int kk = 0; kk < GEMM_BK; kk += 8) {
            uint32_t afr[4][4];
#pragma unroll
            for (int mi = 0; mi < 4; mi++) {
                const int row = warp_m * 64 + mi * 16 + g;
                const float* ap0 = As + row * GEMM_STRIDE + kk + tig;
                const float* ap1 = ap0 + 8 * GEMM_STRIDE;
                afr[mi][0] = __float_as_uint(ap0[0]);
                afr[mi][1] = __float_as_uint(ap1[0]);
                afr[mi][2] = __float_as_uint(ap0[4]);
                afr[mi][3] = __float_as_uint(ap1[4]);
            }
            uint32_t bfr[4][2];
#pragma unroll
            for (int ni = 0; ni < 4; ni++) {
                const int col = warp_n * 32 + ni * 8 + g;
                const float* bp = Bs + col * GEMM_STRIDE + kk + tig;
                bfr[ni][0] = __float_as_uint(bp[0]);
                bfr[ni][1] = __float_as_uint(bp[4]);
            }
#pragma unroll
            for (int mi = 0; mi < 4; mi++)
#pragma unroll
                for (int ni = 0; ni < 4; ni++)
                    mma_tf32(acc[mi][ni], afr[mi], bfr[ni]);
        }
    }

#pragma unroll
    for (int mi = 0; mi < 4; mi++) {
#pragma unroll
        for (int ni = 0; ni < 4; ni++) {
            const int row = by * 128 + warp_m * 64 + mi * 16 + g;
            const int col = bx * 128 + warp_n * 32 + ni * 8 + tig * 2;
            float2 v0 = make_float2(acc[mi][ni][0], acc[mi][ni][1]);
            float2 v1 = make_float2(acc[mi][ni][2], acc[mi][ni][3]);
            if (bias) {
                float2 bb = *(const float2*)(bias + col);
                v0.x += bb.x; v0.y += bb.y;
                v1.x += bb.x; v1.y += bb.y;
            }
            *(float2*)(C + (size_t)row * Ncols + col) = v0;
            *(float2*)(C + (size_t)(row + 8) * Ncols + col) = v1;
        }
    }
}

// ===========================================================================
// tf32 mma.sync flash attention.
// Block: BQ=128 queries for one (b,h), 256 threads = 8 warps (16 rows each).
// Streams 32 KV tiles of 64. Softmax in log2 domain, exp2 on FMA pipe.
// SMEM (floats): Qs[128][68], Ks[64][68], Vs[64][72], Ps[128][68] = 105472 B.
// ===========================================================================
#define AQ_STR 68
#define AV_STR 72
#define ATTN_OFF_K  (128 * AQ_STR)
#define ATTN_OFF_V  (ATTN_OFF_K + 64 * AQ_STR)
#define ATTN_OFF_P  (ATTN_OFF_V + 64 * AV_STR)
#define ATTN_SMEM_F (ATTN_OFF_P + 128 * AQ_STR)
#define ATTN_SMEM   (ATTN_SMEM_F * 4)

__global__ __launch_bounds__(256, 2)
void attn_mma_kernel(const float* __restrict__ qkv, float* __restrict__ outp)
{
    extern __shared__ float sm[];
    float* Qs = sm;
    float* Ks = sm + ATTN_OFF_K;
    float* Vs = sm + ATTN_OFF_V;
    float* Ps = sm + ATTN_OFF_P;

    const int tid = threadIdx.x;
    const int wid = tid >> 5, lid = tid & 31;
    const int g = lid >> 2, tig = lid & 3;
    const int qt = blockIdx.x, h = blockIdx.y, b = blockIdx.z;
    const int br = wid * 16;                       // warp's query-row base
    const size_t rstride = 3 * PDIM;
    const float QF = PSCALE * 1.44269504f;         // fold log2(e) into Q

    // Load Q tile [128][64], scale + rna-round to tf32
    {
        const float* qb = qkv + ((size_t)(b * PN) + qt * 128) * rstride + h * PHD;
#pragma unroll
        for (int i = 0; i < 8; i++) {
            int e = tid + i * 256;
            int r = e >> 4, d = (e & 15) * 4;
            float4 v = *(const float4*)(qb + (size_t)r * rstride + d);
            uint4 u;
            u.x = f2tf32(v.x * QF); u.y = f2tf32(v.y * QF);
            u.z = f2tf32(v.z * QF); u.w = f2tf32(v.w * QF);
            *(uint4*)(Qs + r * AQ_STR + d) = u;
        }
    }

    float o[8][4];
#pragma unroll
    for (int di = 0; di < 8; di++)
#pragma unroll
        for (int j = 0; j < 4; j++) o[di][j] = 0.0f;
    float m0 = -1e30f, m1 = -1e30f, l0 = 0.0f, l1 = 0.0f;

    __syncthreads();

    for (int j0 = 0; j0 < PN; j0 += 64) {
        // Load K[64][64] and V[64][64] tiles (rna-rounded)
        {
            const float* kb = qkv + ((size_t)(b * PN) + j0) * rstride + PDIM + h * PHD;
            const float* vb = kb + PDIM;
#pragma unroll
            for (int i = 0; i < 4; i++) {
                int e = tid + i * 256;
                int r = e >> 4, d = (e & 15) * 4;
                float4 kv = *(const float4*)(kb + (size_t)r * rstride + d);
                uint4 uk;
                uk.x = f2tf32(kv.x); uk.y = f2tf32(kv.y);
                uk.z = f2tf32(kv.z); uk.w = f2tf32(kv.w);
                *(uint4*)(Ks + r * AQ_STR + d) = uk;
                float4 vv = *(const float4*)(vb + (size_t)r * rstride + d);
                uint4 uv;
                uv.x = f2tf32(vv.x); uv.y = f2tf32(vv.y);
                uv.z = f2tf32(vv.z); uv.w = f2tf32(vv.w);
                *(uint4*)(Vs + r * AV_STR + d) = uv;
            }
        }
        __syncthreads();

        // S = Q @ K^T for this warp's 16 rows x 64 cols (log2-domain scores)
        float s[8][4];
#pragma unroll
        for (int ni = 0; ni < 8; ni++)
#pragma unroll
            for (int j = 0; j < 4; j++) s[ni][j] = 0.0f;

#pragma unroll
        for (int kk = 0; kk < 64; kk += 8) {
            uint32_t afr[4];
            const float* ap = Qs + (br + g) * AQ_STR + kk + tig;
            afr[0] = __float_as_uint(ap[0]);
            afr[1] = __float_as_uint(ap[8 * AQ_STR]);
            afr[2] = __float_as_uint(ap[4]);
            afr[3] = __float_as_uint(ap[8 * AQ_STR + 4]);
#pragma unroll
            for (int ni = 0; ni < 8; ni++) {
                const float* bp = Ks + (ni * 8 + g) * AQ_STR + kk + tig;
                uint32_t bfr[2];
                bfr[0] = __float_as_uint(bp[0]);
                bfr[1] = __float_as_uint(bp[4]);
                mma_tf32(s[ni], afr, bfr);
            }
        }

        // Online softmax (rows br+g and br+g+8), log2 domain
        float mx0 = -1e30f, mx1 = -1e30f;
#pragma unroll
        for (int ni = 0; ni < 8; ni++) {
            mx0 = fmaxf(mx0, fmaxf(s[ni][0], s[ni][1]));
            mx1 = fmaxf(mx1, fmaxf(s[ni][2], s[ni][3]));
        }
        mx0 = fmaxf(mx0, __shfl_xor_sync(0xffffffffu, mx0, 1));
        mx0 = fmaxf(mx0, __shfl_xor_sync(0xffffffffu, mx0, 2));
        mx1 = fmaxf(mx1, __shfl_xor_sync(0xffffffffu, mx1, 1));
        mx1 = fmaxf(mx1, __shfl_xor_sync(0xffffffffu, mx1, 2));

        const float nm0 = fmaxf(m0, mx0), nm1 = fmaxf(m1, mx1);
        const float c0 = exp2_fast(m0 - nm0);
        const float c1 = exp2_fast(m1 - nm1);

        float sum0 = 0.0f, sum1 = 0.0f;
#pragma unroll
        for (int ni = 0; ni < 8; ni++) {
            float p0 = __uint_as_float(f2tf32(exp2_fast(s[ni][0] - nm0)));
            float p1 = __uint_as_float(f2tf32(exp2_fast(s[ni][1] - nm0)));
            float p2 = __uint_as_float(f2tf32(exp2_fast(s[ni][2] - nm1)));
            float p3 = __uint_as_float(f2tf32(exp2_fast(s[ni][3] - nm1)));
            sum0 += p0 + p1;
            sum1 += p2 + p3;
            s[ni][0] = p0; s[ni][1] = p1; s[ni][2] = p2; s[ni][3] = p3;
        }
        sum0 += __shfl_xor_sync(0xffffffffu, sum0, 1);
        sum0 += __shfl_xor_sync(0xffffffffu, sum0, 2);
        sum1 += __shfl_xor_sync(0xffffffffu, sum1, 1);
        sum1 += __shfl_xor_sync(0xffffffffu, sum1, 2);

        l0 = l0 * c0 + sum0;  m0 = nm0;
        l1 = l1 * c1 + sum1;  m1 = nm1;

        // Rescale O accumulators
#pragma unroll
        for (int di = 0; di < 8; di++) {
            o[di][0] *= c0; o[di][1] *= c0;
            o[di][2] *= c1; o[di][3] *= c1;
        }

        // Store P (warp-private rows) to SMEM for A-fragment reload
#pragma unroll
        for (int ni = 0; ni < 8; ni++) {
            float* pr0 = Ps + (br + g) * AQ_STR + ni * 8 + 2 * tig;
            float* pr1 = pr0 + 8 * AQ_STR;
            pr0[0] = s[ni][0]; pr0[1] = s[ni][1];
            pr1[0] = s[ni][2]; pr1[1] = s[ni][3];
        }
        __syncwarp();

        // O += P @ V  (n-dim = head dim d via untransposed Vs, stride 72)
#pragma unroll
        for (int kk = 0; kk < 64; kk += 8) {
            uint32_t afr[4];
            const float* ap = Ps + (br + g) * AQ_STR + kk + tig;
            afr[0] = __float_as_uint(ap[0]);
            afr[1] = __float_as_uint(ap[8 * AQ_STR]);
            afr[2] = __float_as_uint(ap[4]);
            afr[3] = __float_as_uint(ap[8 * AQ_STR + 4]);
#pragma unroll
            for (int di = 0; di < 8; di++) {
                const float* bp = Vs + (kk + tig) * AV_STR + di * 8 + g;
                uint32_t bfr[2];
                bfr[0] = __float_as_uint(bp[0]);
                bfr[1] = __float_as_uint(bp[4 * AV_STR]);
                mma_tf32(o[di], afr, bfr);
            }
        }
        __syncthreads();   // before next tile overwrites Ks/Vs
    }

    // Normalize, round to tf32, write out
    {
        const float inv0 = 1.0f / l0, inv1 = 1.0f / l1;
        const size_t row0 = (size_t)(b * PN) + qt * 128 + br + g;
        float* ob = outp + row0 * PDIM + h * PHD;
#pragma unroll
        for (int di = 0; di < 8; di++) {
            uint2 v0, v1;
            v0.x = f2tf32(o[di][0] * inv0);
            v0.y = f2tf32(o[di][1] * inv0);
            v1.x = f2tf32(o[di][2] * inv1);
            v1.y = f2tf32(o[di][3] * inv1);
            *(uint2*)(ob + di * 8 + 2 * tig) = v0;
            *(uint2*)(ob + (size_t)8 * PDIM + di * 8 + 2 * tig) = v1;
        }
    }
}

// ---------------------------------------------------------------------------
// Launch
// ---------------------------------------------------------------------------
extern "C" void kernel_launch(void* const* d_in, const int* in_sizes, int n_in,
                              void* d_out, int out_size)
{
    const float* x      = (const float*)d_in[0];
    const float* w_qkv  = (const float*)d_in[1];
    const float* w_proj = (const float*)d_in[2];
    const float* b_proj = (const float*)d_in[3];
    float* out = (float*)d_out;

    float *qkv = nullptr, *att = nullptr, *xr = nullptr, *wt = nullptr;
    cudaGetSymbolAddress((void**)&qkv, g_qkv);
    cudaGetSymbolAddress((void**)&att, g_attn);
    cudaGetSymbolAddress((void**)&xr,  g_xr);
    cudaGetSymbolAddress((void**)&wt,  g_wt);
    float* wqkvT  = wt;
    float* wprojT = wt + (size_t)3 * PDIM * PDIM;

    cudaFuncSetAttribute(gemm_mma_kernel,
                         cudaFuncAttributeMaxDynamicSharedMemorySize, GEMM_SMEM);
    cudaFuncSetAttribute(attn_mma_kernel,
                         cudaFuncAttributeMaxDynamicSharedMemorySize, ATTN_SMEM);

    const int M = PB * PN;          // 8192

    // 0) pre-round x; transpose+round weights
    {
        int n4 = (int)((size_t)M * PDIM / 4);
        round_tf32_kernel<<<(n4 + 255) / 256, 256>>>(x, xr, n4);
        dim3 blk(32, 8);
        transpose_kernel<<<dim3(3 * PDIM / 32, PDIM / 32), blk>>>(w_qkv, wqkvT, PDIM, 3 * PDIM);
        transpose_kernel<<<dim3(PDIM / 32, PDIM / 32), blk>>>(w_proj, wprojT, PDIM, PDIM);
    }

    // 1) qkv = x @ w_qkv  (tf32 mma)
    {
        dim3 grid(3 * PDIM / 128, M / 128);
        gemm_mma_kernel<<<grid, 256, GEMM_SMEM>>>(xr, wqkvT, qkv, M, 3 * PDIM, PDIM, nullptr);
    }

    // 2) flash attention (tf32 mma)
    {
        dim3 grid(PN / 128, PH, PB);
        attn_mma_kernel<<<grid, 256, ATTN_SMEM>>>(qkv, att);
    }

    // 3) out = att @ w_proj + b_proj  (tf32 mma)
    {
        dim3 grid(PDIM / 128, M / 128);
        gemm_mma_kernel<<<grid, 256, GEMM_SMEM>>>(att, wprojT, out, M, PDIM, PDIM, b_proj);
    }
}

// round 8
// speedup vs baseline: 8.6998x; 2.0582x over previous
#include <cuda_runtime.h>
#include <cuda_fp16.h>
#include <cstdint>
#include <cstddef>

// Problem constants
#define PB   4
#define PN   2048
#define PDIM 1024
#define PH   16
#define PHD  64
#define PSCALE 0.125f           // HEAD_DIM^-0.5

// Scratch (allocation-free rule: __device__ globals)
__device__ __half g_xh[(size_t)PB * PN * PDIM];        // x as fp16
__device__ __half g_qkvh[(size_t)PB * PN * 3 * PDIM];  // qkv as fp16 (Q pre-scaled)
__device__ __half g_atth[(size_t)PB * PN * PDIM];      // attention out as fp16
__device__ __half g_wth[(size_t)4 * PDIM * PDIM];      // transposed weights fp16

// ===========================================================================
// Helpers (baseline PTX only)
// ===========================================================================
__device__ __forceinline__ uint32_t smem_u32(const void* p) {
    uint32_t a;
    asm("{ .reg .u64 t; cvta.to.shared.u64 t, %1; cvt.u32.u64 %0, t; }" : "=r"(a) : "l"(p));
    return a;
}
__device__ __forceinline__ void cp_async16(uint32_t saddr, const void* gptr) {
    asm volatile("cp.async.cg.shared.global [%0], [%1], 16;" :: "r"(saddr), "l"(gptr));
}
#define CP_COMMIT() asm volatile("cp.async.commit_group;" ::: "memory")
#define CP_WAIT1()  asm volatile("cp.async.wait_group 1;" ::: "memory")

#define LDSM_X4(r, addr) \
    asm volatile("ldmatrix.sync.aligned.m8n8.x4.shared.b16 {%0,%1,%2,%3}, [%4];" \
        : "=r"((r)[0]), "=r"((r)[1]), "=r"((r)[2]), "=r"((r)[3]) : "r"(addr))
#define LDSM_X4_T(r, addr) \
    asm volatile("ldmatrix.sync.aligned.m8n8.x4.trans.shared.b16 {%0,%1,%2,%3}, [%4];" \
        : "=r"((r)[0]), "=r"((r)[1]), "=r"((r)[2]), "=r"((r)[3]) : "r"(addr))

// D += A*B  (m16n8k16, fp16 in, fp32 accum)
__device__ __forceinline__ void mma_f16(float* d, const uint32_t* a, const uint32_t* b) {
    asm volatile(
        "mma.sync.aligned.m16n8k16.row.col.f32.f16.f16.f32 "
        "{%0,%1,%2,%3}, {%4,%5,%6,%7}, {%8,%9}, {%0,%1,%2,%3};"
        : "+f"(d[0]), "+f"(d[1]), "+f"(d[2]), "+f"(d[3])
        : "r"(a[0]), "r"(a[1]), "r"(a[2]), "r"(a[3]), "r"(b[0]), "r"(b[1]));
}

__device__ __forceinline__ uint32_t pack_h2(float lo, float hi) {
    __half2 h = __floats2half2_rn(lo, hi);
    return *(uint32_t*)&h;
}

// Fast 2^t on the FMA pipe (no MUFU). t <= 0 expected; clamped at -126.
__device__ __forceinline__ float exp2_fast(float t) {
    t = fmaxf(t, -126.0f);
    int n = __float2int_rn(t);
    float f = t - (float)n;
    float p = 1.0f + f * (0.6931472f + f * (0.2402265f + f * (0.0555041f + f * 0.0096784f)));
    return __uint_as_float(__float_as_uint(p) + ((uint32_t)n << 23));
}

// ===========================================================================
// fp32 -> fp16 convert (vectorized)
// ===========================================================================
__global__ void f32_to_f16_kernel(const float* __restrict__ in, __half* __restrict__ out, int n4)
{
    int i = blockIdx.x * blockDim.x + threadIdx.x;
    if (i < n4) {
        float4 v = ((const float4*)in)[i];
        uint2 r;
        r.x = pack_h2(v.x, v.y);
        r.y = pack_h2(v.z, v.w);
        ((uint2*)out)[i] = r;
    }
}

// ===========================================================================
// Transpose fp32 -> fp16: out[C][R] = h(in[R][C] * (col<scaleN ? scale : 1))
// ===========================================================================
__global__ void transpose_h_kernel(const float* __restrict__ in, __half* __restrict__ out,
                                   int R, int C, int scaleN, float scale)
{
    __shared__ float t[32][33];
    int bx = blockIdx.x, by = blockIdx.y;
    int tx = threadIdx.x, ty = threadIdx.y;
#pragma unroll
    for (int j = 0; j < 32; j += 8)
        t[ty + j][tx] = in[(size_t)(by * 32 + ty + j) * C + bx * 32 + tx];
    __syncthreads();
#pragma unroll
    for (int j = 0; j < 32; j += 8) {
        int oc = bx * 32 + ty + j;     // original col = out row
        float s = (oc < scaleN) ? scale : 1.0f;
        out[(size_t)oc * R + by * 32 + tx] = __float2half_rn(t[tx][ty + j] * s);
    }
}

// ===========================================================================
// fp16 mma GEMM:  C[M, Ncols] = A[M, K] @ Bt[Ncols, K]^T  (+ bias)
// A, Bt row-major fp16. Tile 128x128, BK=32 halfs, 3-stage cp.async,
// 256 threads (8 warps 2x4), warp tile 64x32, m16n8k16 via ldmatrix.
// SMEM row stride 40 halfs (80 B) — ldmatrix conflict-free (80/16 odd).
// ===========================================================================
#define GH_STR_B   80                        // bytes per smem row
#define GH_TILE_B  (128 * GH_STR_B)          // 10240
#define GH_STAGE_B (2 * GH_TILE_B)           // 20480
#define GH_SMEM    (3 * GH_STAGE_B)          // 61440

template<bool HALF_OUT>
__global__ __launch_bounds__(256)
void gemm_f16_kernel(const __half* __restrict__ A, const __half* __restrict__ Bt,
                     void* __restrict__ Cv, int M, int Ncols, int K,
                     const float* __restrict__ bias)
{
    extern __shared__ char smem[];
    const uint32_t smb = smem_u32(smem);
    const int tid = threadIdx.x;
    const int wid = tid >> 5, lid = tid & 31;
    const int warp_m = wid & 1, warp_n = wid >> 1;
    const int g = lid >> 2, tig = lid & 3;
    const int bx = blockIdx.x, by = blockIdx.y;

    const __half* Ab = A  + (size_t)(by * 128) * K;
    const __half* Bb = Bt + (size_t)(bx * 128) * K;

    // cp.async mapping: 512 chunks of 16B per operand, 2/thread
    const int r0 = tid >> 2, cc = tid & 3;

    float acc[4][4][4];
#pragma unroll
    for (int mi = 0; mi < 4; mi++)
#pragma unroll
        for (int ni = 0; ni < 4; ni++)
#pragma unroll
            for (int j = 0; j < 4; j++) acc[mi][ni][j] = 0.0f;

    const int niter = K / 32;

    auto issue = [&](int s, int it) {
        const uint32_t sa = smb + s * GH_STAGE_B;
        const uint32_t sb = sa + GH_TILE_B;
        const size_t k0 = (size_t)it * 32;
        cp_async16(sa + r0 * GH_STR_B + cc * 16,         Ab + (size_t)r0 * K + k0 + cc * 8);
        cp_async16(sa + (r0 + 64) * GH_STR_B + cc * 16,  Ab + (size_t)(r0 + 64) * K + k0 + cc * 8);
        cp_async16(sb + r0 * GH_STR_B + cc * 16,         Bb + (size_t)r0 * K + k0 + cc * 8);
        cp_async16(sb + (r0 + 64) * GH_STR_B + cc * 16,  Bb + (size_t)(r0 + 64) * K + k0 + cc * 8);
    };

    issue(0, 0); CP_COMMIT();
    issue(1, 1); CP_COMMIT();

    for (int it = 0; it < niter; it++) {
        CP_WAIT1();
        __syncthreads();
        if (it + 2 < niter) issue((it + 2) % 3, it + 2);
        CP_COMMIT();

        const uint32_t sA = smb + (it % 3) * GH_STAGE_B;
        const uint32_t sB = sA + GH_TILE_B;

#pragma unroll
        for (int kk2 = 0; kk2 < 2; kk2++) {            // k16 steps; byte off kk2*32
            uint32_t af[4][4];
#pragma unroll
            for (int mi = 0; mi < 4; mi++) {
                uint32_t addr = sA + (warp_m * 64 + mi * 16 + (lid & 15)) * GH_STR_B
                              + kk2 * 32 + (lid >> 4) * 16;
                LDSM_X4(af[mi], addr);
            }
            uint32_t bf[2][4];
#pragma unroll
            for (int nb = 0; nb < 2; nb++) {
                uint32_t addr = sB + (warp_n * 32 + nb * 16 + (lid & 7) + (lid >> 4) * 8) * GH_STR_B
                              + kk2 * 32 + ((lid >> 3) & 1) * 16;
                LDSM_X4(bf[nb], addr);
            }
#pragma unroll
            for (int mi = 0; mi < 4; mi++)
#pragma unroll
                for (int ni = 0; ni < 4; ni++)
                    mma_f16(acc[mi][ni], af[mi], bf[ni >> 1] + (ni & 1) * 2);
        }
    }

    // Epilogue: c0,c1 at (row, 2tig), c2,c3 at (row+8, 2tig)
#pragma unroll
    for (int mi = 0; mi < 4; mi++) {
#pragma unroll
        for (int ni = 0; ni < 4; ni++) {
            const int row = by * 128 + warp_m * 64 + mi * 16 + g;
            const int col = bx * 128 + warp_n * 32 + ni * 8 + tig * 2;
            if (HALF_OUT) {
                __half* C = (__half*)Cv;
                *(uint32_t*)(C + (size_t)row * Ncols + col) =
                    pack_h2(acc[mi][ni][0], acc[mi][ni][1]);
                *(uint32_t*)(C + (size_t)(row + 8) * Ncols + col) =
                    pack_h2(acc[mi][ni][2], acc[mi][ni][3]);
            } else {
                float* C = (float*)Cv;
                float2 v0 = make_float2(acc[mi][ni][0], acc[mi][ni][1]);
                float2 v1 = make_float2(acc[mi][ni][2], acc[mi][ni][3]);
                if (bias) {
                    float2 bb = *(const float2*)(bias + col);
                    v0.x += bb.x; v0.y += bb.y;
                    v1.x += bb.x; v1.y += bb.y;
                }
                *(float2*)(C + (size_t)row * Ncols + col) = v0;
                *(float2*)(C + (size_t)(row + 8) * Ncols + col) = v1;
            }
        }
    }
}

// ===========================================================================
// fp16 mma flash attention.
// BQ=128, BKV=64, 256 threads (8 warps x 16 rows). Q pre-scaled by
// SCALE*log2e (folded into w_qkv), softmax in log2 domain via exp2 on FMA.
// P stays in registers (QK^T C-frag == PV A-frag layout). V via ldmatrix.trans.
// Row = 64 halfs = 128 B; stride 144 B (>=128, 144/16 odd -> conflict-free).
// SMEM: Q 128 rows + 3 stages x (K 64 + V 64 rows) = 4 * 18432 = 73728 B.
// ===========================================================================
#define AT_STR_B    144
#define AT_Q_B      (128 * AT_STR_B)         // 18432
#define AT_KV_B     (128 * AT_STR_B)         // K tile + V tile per stage
#define AT_SMEM     (AT_Q_B + 3 * AT_KV_B)   // 73728

__global__ __launch_bounds__(256, 2)
void attn_f16_kernel(const __half* __restrict__ qkv, __half* __restrict__ outp)
{
    extern __shared__ char smc[];
    const uint32_t smb = smem_u32(smc);
    const int tid = threadIdx.x;
    const int wid = tid >> 5, lid = tid & 31;
    const int g = lid >> 2, tig = lid & 3;
    const int qt = blockIdx.x, h = blockIdx.y, b = blockIdx.z;
    const int br = wid * 16;
    const size_t rstride = 3 * PDIM;

    const __half* qb = qkv + ((size_t)(b * PN) + qt * 128) * rstride + h * PHD;

    // cp.async chunk mapping (rows of 128 B = 8 chunks)
    auto issueKV = [&](int jt, int s) {
        const __half* kb = qkv + ((size_t)(b * PN) + jt * 64) * rstride + PDIM + h * PHD;
        const __half* vb = kb + PDIM;
        const uint32_t kS = smb + AT_Q_B + s * AT_KV_B;
        const uint32_t vS = kS + 64 * AT_STR_B;
#pragma unroll
        for (int i = 0; i < 2; i++) {
            int c = tid + i * 256;
            int r = c >> 3, cx = c & 7;
            cp_async16(kS + r * AT_STR_B + cx * 16, kb + (size_t)r * rstride + cx * 8);
            cp_async16(vS + r * AT_STR_B + cx * 16, vb + (size_t)r * rstride + cx * 8);
        }
    };

    // Q (group 0, together with KV tile 0)
#pragma unroll
    for (int i = 0; i < 4; i++) {
        int c = tid + i * 256;
        int r = c >> 3, cx = c & 7;
        cp_async16(smb + r * AT_STR_B + cx * 16, qb + (size_t)r * rstride + cx * 8);
    }
    issueKV(0, 0); CP_COMMIT();
    issueKV(1, 1); CP_COMMIT();

    float o[8][4];
#pragma unroll
    for (int di = 0; di < 8; di++)
#pragma unroll
        for (int j = 0; j < 4; j++) o[di][j] = 0.0f;
    float m0 = -1e30f, m1 = -1e30f, l0 = 0.0f, l1 = 0.0f;

    const int nt = PN / 64;      // 32
    for (int jt = 0; jt < nt; jt++) {
        CP_WAIT1();
        __syncthreads();
        if (jt + 2 < nt) issueKV(jt + 2, (jt + 2) % 3);
        CP_COMMIT();

        const uint32_t kS = smb + AT_Q_B + (jt % 3) * AT_KV_B;
        const uint32_t vS = kS + 64 * AT_STR_B;

        // S = Q @ K^T : warp rows br..br+15 x 64 keys (log2-domain scores)
        float sc[8][4];
#pragma unroll
        for (int ni = 0; ni < 8; ni++)
#pragma unroll
            for (int j = 0; j < 4; j++) sc[ni][j] = 0.0f;

#pragma unroll
        for (int kt = 0; kt < 4; kt++) {      // d chunks of 16
            uint32_t a[4];
            uint32_t aaddr = smb + (br + (lid & 15)) * AT_STR_B + kt * 32 + (lid >> 4) * 16;
            LDSM_X4(a, aaddr);
#pragma unroll
            for (int nb = 0; nb < 4; nb++) {  // key-tile pairs (16 keys)
                uint32_t bb[4];
                uint32_t baddr = kS + (nb * 16 + (lid & 7) + (lid >> 4) * 8) * AT_STR_B
                               + kt * 32 + ((lid >> 3) & 1) * 16;
                LDSM_X4(bb, baddr);
                mma_f16(sc[2 * nb],     a, bb);
                mma_f16(sc[2 * nb + 1], a, bb + 2);
            }
        }

        // Online softmax (rows br+g and br+g+8)
        float mx0 = -1e30f, mx1 = -1e30f;
#pragma unroll
        for (int ni = 0; ni < 8; ni++) {
            mx0 = fmaxf(mx0, fmaxf(sc[ni][0], sc[ni][1]));
            mx1 = fmaxf(mx1, fmaxf(sc[ni][2], sc[ni][3]));
        }
        mx0 = fmaxf(mx0, __shfl_xor_sync(0xffffffffu, mx0, 1));
        mx0 = fmaxf(mx0, __shfl_xor_sync(0xffffffffu, mx0, 2));
        mx1 = fmaxf(mx1, __shfl_xor_sync(0xffffffffu, mx1, 1));
        mx1 = fmaxf(mx1, __shfl_xor_sync(0xffffffffu, mx1, 2));

        const float nm0 = fmaxf(m0, mx0), nm1 = fmaxf(m1, mx1);
        const float c0 = exp2_fast(m0 - nm0);
        const float c1 = exp2_fast(m1 - nm1);

        // exp2, pack P to A-fragments, sum the half-rounded values
        uint32_t pa[4][4];
        float sum0 = 0.0f, sum1 = 0.0f;
#pragma unroll
        for (int ni = 0; ni < 8; ni++) {
            float p0 = exp2_fast(sc[ni][0] - nm0);
            float p1 = exp2_fast(sc[ni][1] - nm0);
            float p2 = exp2_fast(sc[ni][2] - nm1);
            float p3 = exp2_fast(sc[ni][3] - nm1);
            uint32_t u01 = pack_h2(p0, p1);
            uint32_t u23 = pack_h2(p2, p3);
            const int kt = ni >> 1, half_sel = ni & 1;
            pa[kt][half_sel * 2 + 0] = u01;
            pa[kt][half_sel * 2 + 1] = u23;
            float2 f01 = __half22float2(*(__half2*)&u01);
            float2 f23 = __half22float2(*(__half2*)&u23);
            sum0 += f01.x + f01.y;
            sum1 += f23.x + f23.y;
        }
        sum0 += __shfl_xor_sync(0xffffffffu, sum0, 1);
        sum0 += __shfl_xor_sync(0xffffffffu, sum0, 2);
        sum1 += __shfl_xor_sync(0xffffffffu, sum1, 1);
        sum1 += __shfl_xor_sync(0xffffffffu, sum1, 2);

        l0 = l0 * c0 + sum0;  m0 = nm0;
        l1 = l1 * c1 + sum1;  m1 = nm1;

#pragma unroll
        for (int di = 0; di < 8; di++) {
            o[di][0] *= c0; o[di][1] *= c0;
            o[di][2] *= c1; o[di][3] *= c1;
        }

        // O += P @ V   (A-frag pa[kt] from registers; B-frag via ldmatrix.trans)
#pragma unroll
        for (int kt = 0; kt < 4; kt++) {      // key chunks of 16
#pragma unroll
            for (int db = 0; db < 4; db++) {  // d-tile pairs (16 d)
                uint32_t vv[4];
                uint32_t vaddr = vS + (kt * 16 + (lid & 7) + ((lid >> 3) & 1) * 8) * AT_STR_B
                               + db * 32 + (lid >> 4) * 16;
                LDSM_X4_T(vv, vaddr);
                mma_f16(o[2 * db],     pa[kt], vv);
                mma_f16(o[2 * db + 1], pa[kt], vv + 2);
            }
        }
    }

    // Normalize, write half
    {
        const float inv0 = 1.0f / l0, inv1 = 1.0f / l1;
        const size_t row0 = (size_t)(b * PN) + qt * 128 + br + g;
        __half* ob = outp + row0 * PDIM + h * PHD;
#pragma unroll
        for (int di = 0; di < 8; di++) {
            *(uint32_t*)(ob + di * 8 + 2 * tig) =
                pack_h2(o[di][0] * inv0, o[di][1] * inv0);
            *(uint32_t*)(ob + (size_t)8 * PDIM + di * 8 + 2 * tig) =
                pack_h2(o[di][2] * inv1, o[di][3] * inv1);
        }
    }
}

// ---------------------------------------------------------------------------
// Launch
// ---------------------------------------------------------------------------
extern "C" void kernel_launch(void* const* d_in, const int* in_sizes, int n_in,
                              void* d_out, int out_size)
{
    const float* x      = (const float*)d_in[0];
    const float* w_qkv  = (const float*)d_in[1];
    const float* w_proj = (const float*)d_in[2];
    const float* b_proj = (const float*)d_in[3];
    float* out = (float*)d_out;

    __half *xh = nullptr, *qkvh = nullptr, *atth = nullptr, *wth = nullptr;
    cudaGetSymbolAddress((void**)&xh,   g_xh);
    cudaGetSymbolAddress((void**)&qkvh, g_qkvh);
    cudaGetSymbolAddress((void**)&atth, g_atth);
    cudaGetSymbolAddress((void**)&wth,  g_wth);
    __half* wqkvT  = wth;                             // [3072][1024]
    __half* wprojT = wth + (size_t)3 * PDIM * PDIM;   // [1024][1024]

    cudaFuncSetAttribute(gemm_f16_kernel<true>,
                         cudaFuncAttributeMaxDynamicSharedMemorySize, GH_SMEM);
    cudaFuncSetAttribute(gemm_f16_kernel<false>,
                         cudaFuncAttributeMaxDynamicSharedMemorySize, GH_SMEM);
    cudaFuncSetAttribute(attn_f16_kernel,
                         cudaFuncAttributeMaxDynamicSharedMemorySize, AT_SMEM);

    const int M = PB * PN;                  // 8192
    const float QF = PSCALE * 1.44269504f;  // fold scale*log2(e) into Q weights

    // 0) convert x; transpose weights (Q-cols of w_qkv scaled by QF)
    {
        int n4 = (int)((size_t)M * PDIM / 4);
        f32_to_f16_kernel<<<(n4 + 255) / 256, 256>>>(x, xh, n4);
        dim3 blk(32, 8);
        transpose_h_kernel<<<dim3(3 * PDIM / 32, PDIM / 32), blk>>>(w_qkv, wqkvT, PDIM, 3 * PDIM, PDIM, QF);
        transpose_h_kernel<<<dim3(PDIM / 32, PDIM / 32), blk>>>(w_proj, wprojT, PDIM, PDIM, 0, 1.0f);
    }

    // 1) qkv = x @ w_qkv  (fp16 mma, half out)
    {
        dim3 grid(3 * PDIM / 128, M / 128);
        gemm_f16_kernel<true><<<grid, 256, GH_SMEM>>>(xh, wqkvT, qkvh, M, 3 * PDIM, PDIM, nullptr);
    }

    // 2) flash attention (fp16 mma)
    {
        dim3 grid(PN / 128, PH, PB);
        attn_f16_kernel<<<grid, 256, AT_SMEM>>>(qkvh, atth);
    }

    // 3) out = att @ w_proj + b_proj  (fp16 mma, fp32 out)
    {
        dim3 grid(PDIM / 128, M / 128);
        gemm_f16_kernel<false><<<grid, 256, GH_SMEM>>>(atth, wprojT, out, M, PDIM, PDIM, b_proj);
    }
}